// round 5
// baseline (speedup 1.0000x reference)
#include <cuda_runtime.h>
#include <math.h>
#include <stdint.h>

#define NP 500000
#define NQ 200000
#define CDIM 64
#define EMAX 1200000

// ------------------------- scratch (static device globals) -------------------------
__device__ float g_hsP[(size_t)NP * CDIM];   // hs for conv src=person
__device__ float g_hsQ[(size_t)NQ * CDIM];   // hs for conv src=product
__device__ float g_hp1[(size_t)NP * CDIM];   // layer-0 person output
__device__ float g_hq1[(size_t)NQ * CDIM];   // layer-0 product output
__device__ float g_alsP[NP], g_aldP[NP], g_denP[NP];
__device__ float g_alsQ[NQ], g_aldQ[NQ], g_denQ[NQ];
__device__ float g_e0[EMAX];                 // ebuf conv0 (P->Q)
__device__ float g_e1[EMAX];                 // ebuf conv1 (Q->P)

// ------------------------- f32x2 packed-FMA helpers -------------------------
__device__ __forceinline__ unsigned long long pack2(float lo, float hi) {
    unsigned long long r;
    asm("mov.b64 %0, {%1, %2};" : "=l"(r) : "f"(lo), "f"(hi));
    return r;
}
__device__ __forceinline__ void fma2(unsigned long long& acc, unsigned long long a,
                                     unsigned long long b) {
    asm("fma.rn.f32x2 %0, %1, %2, %0;" : "+l"(acc) : "l"(a), "l"(b));
}
__device__ __forceinline__ float2 unpack2(unsigned long long v) {
    float lo, hi;
    asm("mov.b64 {%0, %1}, %2;" : "=f"(lo), "=f"(hi) : "l"(v));
    return make_float2(lo, hi);
}

// ------------------------- kernels -------------------------

// H = f(X) @ W  (f = ELU if flag), fused:
//   als = H @ avs                          (this conv, X as src)
//   ald = f(X) @ (Wd_other @ avd_other)    (other conv, X as dst) — wvec built per block
template <bool ELU>
__global__ __launch_bounds__(128) void gemm_kernel(
    const float* __restrict__ X, const float* __restrict__ W,
    const float* __restrict__ avs,
    const float* __restrict__ Wd_o, const float* __restrict__ avd_o,
    float* __restrict__ H, float* __restrict__ als, float* __restrict__ ald, int N)
{
    __shared__ float xT[64 * 128];   // [k][row] transposed, 32KB
    __shared__ float ws[64 * 64];    // [k][c], 16KB
    __shared__ float wv[64];
    const int tid  = threadIdx.x;
    const int row0 = blockIdx.x * 128;

    if (tid < 64) {
        float s = 0.f;
        #pragma unroll
        for (int c = 0; c < CDIM; c++) s = fmaf(__ldg(&Wd_o[tid * CDIM + c]), __ldg(&avd_o[c]), s);
        wv[tid] = s;
    }
    {
        const float4* Wv = (const float4*)W;
        float4* wsv = (float4*)ws;
        #pragma unroll
        for (int i = 0; i < 8; i++) wsv[i * 128 + tid] = Wv[i * 128 + tid];
    }
    {
        int row = row0 + tid;
        if (row < N) {
            const float4* Xv = (const float4*)(X + (size_t)row * CDIM);
            #pragma unroll
            for (int j = 0; j < 16; j++) {
                float4 v = Xv[j];
                if (ELU) {
                    v.x = (v.x > 0.f) ? v.x : expm1f(v.x);
                    v.y = (v.y > 0.f) ? v.y : expm1f(v.y);
                    v.z = (v.z > 0.f) ? v.z : expm1f(v.z);
                    v.w = (v.w > 0.f) ? v.w : expm1f(v.w);
                }
                xT[(4 * j + 0) * 128 + tid] = v.x;
                xT[(4 * j + 1) * 128 + tid] = v.y;
                xT[(4 * j + 2) * 128 + tid] = v.z;
                xT[(4 * j + 3) * 128 + tid] = v.w;
            }
        } else {
            #pragma unroll
            for (int j = 0; j < 64; j++) xT[j * 128 + tid] = 0.f;
        }
    }
    __syncthreads();

    const int ty = tid >> 3;
    const int tx = tid & 7;
    unsigned long long acc[8][4];
    #pragma unroll
    for (int i = 0; i < 8; i++)
        #pragma unroll
        for (int j = 0; j < 4; j++) acc[i][j] = 0ull;

    #pragma unroll 4
    for (int k = 0; k < 64; k++) {
        float4 a0 = *(const float4*)&xT[k * 128 + ty * 8];
        float4 a1 = *(const float4*)&xT[k * 128 + ty * 8 + 4];
        float4 b0 = *(const float4*)&ws[k * 64 + tx * 8];
        float4 b1 = *(const float4*)&ws[k * 64 + tx * 8 + 4];
        unsigned long long bp[4] = {pack2(b0.x, b0.y), pack2(b0.z, b0.w),
                                    pack2(b1.x, b1.y), pack2(b1.z, b1.w)};
        float a[8] = {a0.x, a0.y, a0.z, a0.w, a1.x, a1.y, a1.z, a1.w};
        #pragma unroll
        for (int i = 0; i < 8; i++) {
            unsigned long long ap = pack2(a[i], a[i]);
            #pragma unroll
            for (int j = 0; j < 4; j++) fma2(acc[i][j], ap, bp[j]);
        }
    }

    unsigned long long avp[4];
    {
        float4 av0 = __ldg((const float4*)avs + tx * 2);
        float4 av1 = __ldg((const float4*)avs + tx * 2 + 1);
        avp[0] = pack2(av0.x, av0.y); avp[1] = pack2(av0.z, av0.w);
        avp[2] = pack2(av1.x, av1.y); avp[3] = pack2(av1.z, av1.w);
    }

    #pragma unroll
    for (int i = 0; i < 8; i++) {
        int row = row0 + ty * 8 + i;
        unsigned long long alp = 0ull;
        #pragma unroll
        for (int j = 0; j < 4; j++) fma2(alp, acc[i][j], avp[j]);
        float2 f = unpack2(alp);
        float al = f.x + f.y;
        al += __shfl_down_sync(0xffffffffu, al, 4);
        al += __shfl_down_sync(0xffffffffu, al, 2);
        al += __shfl_down_sync(0xffffffffu, al, 1);
        if (row < N) {
            ulonglong2* Hp = (ulonglong2*)(H + (size_t)row * CDIM + tx * 8);
            Hp[0] = make_ulonglong2(acc[i][0], acc[i][1]);
            Hp[1] = make_ulonglong2(acc[i][2], acc[i][3]);
            if (tx == 0) als[row] = al;
        }
    }

    {
        float s = 0.f;
        #pragma unroll
        for (int k = 0; k < 64; k++) s = fmaf(xT[k * 128 + tid], wv[k], s);
        int row = row0 + tid;
        if (row < N) ald[row] = s;
    }
}

// merged init for both convs of a layer:
//   out_p rows <- bias_p, out_q rows <- bias_q (float4 broadcast); denP/denQ <- 0
__global__ void initPQ_kernel(float4* __restrict__ out_p, const float* __restrict__ bias_p,
                              float4* __restrict__ out_q, const float* __restrict__ bias_q,
                              float* __restrict__ denP, float* __restrict__ denQ) {
    int i = blockIdx.x * blockDim.x + threadIdx.x;
    const int nP4 = NP * 16, nQ4 = NQ * 16;
    if (i < nP4) out_p[i] = __ldg((const float4*)bias_p + (i & 15));
    else if (i < nP4 + nQ4) out_q[i - nP4] = __ldg((const float4*)bias_q + (i & 15));
    if (i < NP) denP[i] = 0.f;
    else if (i < NP + NQ) denQ[i - NP] = 0.f;
}

// merged edge pass for both convs: ex = exp(leaky_relu(als[src]+ald[dst])); den[dst] += ex
__global__ void edgeAB2_kernel(
    const int* __restrict__ s0, const int* __restrict__ d0,
    const float* __restrict__ als0, const float* __restrict__ ald0,
    float* __restrict__ den0, float* __restrict__ eb0,
    const int* __restrict__ s1, const int* __restrict__ d1,
    const float* __restrict__ als1, const float* __restrict__ ald1,
    float* __restrict__ den1, float* __restrict__ eb1, int E)
{
    int i = blockIdx.x * blockDim.x + threadIdx.x;
    const int* src; const int* dst; const float* als; const float* ald;
    float* den; float* eb;
    if (i < E) { src = s0; dst = d0; als = als0; ald = ald0; den = den0; eb = eb0; }
    else       { i -= E; if (i >= E) return;
                 src = s1; dst = d1; als = als1; ald = ald1; den = den1; eb = eb1; }
    int d = __ldg(&dst[i]);
    float v = __ldg(&als[__ldg(&src[i])]) + __ldg(&ald[d]);
    v = (v >= 0.f) ? v : 0.2f * v;
    float ex = __expf(fminf(v, 80.f));
    eb[i] = ex;
    atomicAdd(&den[d], ex);
}

// scatter: out[dst] += (ex/den[dst]) * hs[src] — 16 threads/edge, float4 vector reds
__global__ void edgeC_kernel(const int* __restrict__ src, const int* __restrict__ dst,
                             const float* __restrict__ ebuf, const float* __restrict__ den,
                             const float* __restrict__ hs, float* __restrict__ out, int E) {
    int t = blockIdx.x * blockDim.x + threadIdx.x;
    int e = t >> 4;
    if (e >= E) return;
    int part = t & 15;
    int s = __ldg(&src[e]);
    int d = __ldg(&dst[e]);
    float alpha = __fdividef(__ldg(&ebuf[e]), __ldg(&den[d]));
    float4 h = __ldg((const float4*)(hs + (size_t)s * CDIM) + part);
    atomicAdd((float4*)(out + (size_t)d * CDIM) + part,
              make_float4(alpha * h.x, alpha * h.y, alpha * h.z, alpha * h.w));
}

// in-place ELU, float4
__global__ void elu4_kernel(float4* __restrict__ p, long n4) {
    long i = (long)blockIdx.x * blockDim.x + threadIdx.x;
    if (i >= n4) return;
    float4 v = p[i];
    v.x = (v.x > 0.f) ? v.x : expm1f(v.x);
    v.y = (v.y > 0.f) ? v.y : expm1f(v.y);
    v.z = (v.z > 0.f) ? v.z : expm1f(v.z);
    v.w = (v.w > 0.f) ? v.w : expm1f(v.w);
    p[i] = v;
}

// ------------------------- host orchestration -------------------------
struct Bufs {
    float *hsP, *hsQ, *alsP, *aldP, *denP, *alsQ, *aldQ, *denQ, *e0, *e1;
};

template <bool ELU>
static void run_layer(const Bufs& B,
                      const float* in_p, const float* in_q,
                      float* out_p, float* out_q,
                      const int* pv_s, const int* pv_d,
                      const int* vp_s, const int* vp_d, int E,
                      const float* Wsrc, const float* Wdst,
                      const float* asrc, const float* adst, const float* bias, int l)
{
    const unsigned gP = (NP + 127) / 128, gQ = (NQ + 127) / 128;
    const unsigned gI = ((NP + NQ) * 16 + 255) / 256;
    const unsigned gE2 = (2 * E + 255) / 256;
    const unsigned gC = (unsigned)(((long)E * 16 + 255) / 256);

    // gemmP: hsP=f(in_p)@Ws0, alsP (conv0 src), aldP=f(in_p)@(Wd1@ad1) (conv1 dst)
    gemm_kernel<ELU><<<gP, 128>>>(in_p, Wsrc + (size_t)(2 * l) * 4096, asrc + (2 * l) * 64,
                                  Wdst + (size_t)(2 * l + 1) * 4096, adst + (2 * l + 1) * 64,
                                  B.hsP, B.alsP, B.aldP, NP);
    // gemmQ last so hsQ is freshest in L2 for edgeC1 below
    gemm_kernel<ELU><<<gQ, 128>>>(in_q, Wsrc + (size_t)(2 * l + 1) * 4096, asrc + (2 * l + 1) * 64,
                                  Wdst + (size_t)(2 * l) * 4096, adst + (2 * l) * 64,
                                  B.hsQ, B.alsQ, B.aldQ, NQ);
    initPQ_kernel<<<gI, 256>>>((float4*)out_p, bias + (2 * l + 1) * 64,
                               (float4*)out_q, bias + (2 * l) * 64, B.denP, B.denQ);
    edgeAB2_kernel<<<gE2, 256>>>(pv_s, pv_d, B.alsP, B.aldQ, B.denQ, B.e0,
                                 vp_s, vp_d, B.alsQ, B.aldP, B.denP, B.e1, E);
    // conv1 first: gathers hsQ (51MB, L2-resident); then conv0 streams hsP (128MB)
    edgeC_kernel<<<gC, 256>>>(vp_s, vp_d, B.e1, B.denP, B.hsQ, out_p, E);
    edgeC_kernel<<<gC, 256>>>(pv_s, pv_d, B.e0, B.denQ, B.hsP, out_q, E);
}

extern "C" void kernel_launch(void* const* d_in, const int* in_sizes, int n_in,
                              void* d_out, int out_size)
{
    const float* xp   = (const float*)d_in[0];
    const float* xq   = (const float*)d_in[1];
    const int*   pv_s = (const int*)d_in[2];
    const int*   pv_d = (const int*)d_in[3];
    const int*   vp_s = (const int*)d_in[4];
    const int*   vp_d = (const int*)d_in[5];
    const float* Wsrc = (const float*)d_in[6];
    const float* Wdst = (const float*)d_in[7];
    const float* asrc = (const float*)d_in[8];
    const float* adst = (const float*)d_in[9];
    const float* bias = (const float*)d_in[10];
    int E = in_sizes[2];

    Bufs B;
    float *hp1, *hq1;
    cudaGetSymbolAddress((void**)&B.hsP,  g_hsP);
    cudaGetSymbolAddress((void**)&B.hsQ,  g_hsQ);
    cudaGetSymbolAddress((void**)&hp1,    g_hp1);
    cudaGetSymbolAddress((void**)&hq1,    g_hq1);
    cudaGetSymbolAddress((void**)&B.alsP, g_alsP);
    cudaGetSymbolAddress((void**)&B.aldP, g_aldP);
    cudaGetSymbolAddress((void**)&B.denP, g_denP);
    cudaGetSymbolAddress((void**)&B.alsQ, g_alsQ);
    cudaGetSymbolAddress((void**)&B.aldQ, g_aldQ);
    cudaGetSymbolAddress((void**)&B.denQ, g_denQ);
    cudaGetSymbolAddress((void**)&B.e0,   g_e0);
    cudaGetSymbolAddress((void**)&B.e1,   g_e1);

    float* outp = (float*)d_out;                       // persons  [NP*64]
    float* outq = (float*)d_out + (size_t)NP * CDIM;   // products [NQ*64]

    // layer 0: raw inputs -> intermediates (ELU folded into layer-1 GEMM loads)
    run_layer<false>(B, xp, xq, hp1, hq1, pv_s, pv_d, vp_s, vp_d, E,
                     Wsrc, Wdst, asrc, adst, bias, 0);
    // layer 1: ELU'd intermediates -> d_out
    run_layer<true>(B, hp1, hq1, outp, outq, pv_s, pv_d, vp_s, vp_d, E,
                    Wsrc, Wdst, asrc, adst, bias, 1);
    // final ELU over the whole contiguous output
    long n4 = (long)(NP + NQ) * CDIM / 4;
    elu4_kernel<<<(unsigned)((n4 + 255) / 256), 256>>>((float4*)d_out, n4);
}

// round 6
// speedup vs baseline: 1.1313x; 1.1313x over previous
#include <cuda_runtime.h>
#include <math.h>
#include <stdint.h>

#define NP 500000
#define NQ 200000
#define CDIM 64
#define EMAX 1200000

// padded sizes for the 1024-per-block scan
#define NQPAD 200704   // 196 * 1024
#define NPPAD 500736   // 489 * 1024
#define MQ 196
#define MP 489

// ------------------------- scratch (static device globals) -------------------------
__device__ float g_hsP[(size_t)NP * CDIM];
__device__ float g_hsQ[(size_t)NQ * CDIM];
__device__ float g_hp1[(size_t)NP * CDIM];
__device__ float g_hq1[(size_t)NQ * CDIM];
__device__ float g_alsP[NP], g_aldP[NP];
__device__ float g_alsQ[NQ], g_aldQ[NQ];
__device__ float g_wvec[128];
// CSR scratch
__device__ int g_cntQ[NQPAD], g_cntP[NPPAD];
__device__ int g_rowQ[NQPAD], g_rowP[NPPAD];
__device__ int g_curQ[NQPAD], g_curP[NPPAD];
__device__ int g_partQ[1024], g_partP[1024];
__device__ int g_ssrc0[EMAX];   // conv0 (P->Q): person srcs sorted by product dst
__device__ int g_ssrc1[EMAX];   // conv1 (Q->P): product srcs sorted by person dst

// ------------------------- f32x2 packed-FMA helpers -------------------------
__device__ __forceinline__ unsigned long long pack2(float lo, float hi) {
    unsigned long long r;
    asm("mov.b64 %0, {%1, %2};" : "=l"(r) : "f"(lo), "f"(hi));
    return r;
}
__device__ __forceinline__ void fma2(unsigned long long& acc, unsigned long long a,
                                     unsigned long long b) {
    asm("fma.rn.f32x2 %0, %1, %2, %0;" : "+l"(acc) : "l"(a), "l"(b));
}
__device__ __forceinline__ float2 unpack2(unsigned long long v) {
    float lo, hi;
    asm("mov.b64 {%0, %1}, %2;" : "=f"(lo), "=f"(hi) : "l"(v));
    return make_float2(lo, hi);
}

// ------------------------- CSR build kernels -------------------------
__global__ void zero_kernel(int* __restrict__ cQ, int* __restrict__ cP) {
    int i = blockIdx.x * blockDim.x + threadIdx.x;
    if (i < NQPAD) cQ[i] = 0;
    else if (i < NQPAD + NPPAD) cP[i - NQPAD] = 0;
}

__global__ void hist_kernel(const int* __restrict__ pv_d, const int* __restrict__ vp_d,
                            int* __restrict__ cntQ, int* __restrict__ cntP, int E) {
    int i = blockIdx.x * blockDim.x + threadIdx.x;
    if (i < E) atomicAdd(&cntQ[__ldg(&pv_d[i])], 1);
    else if (i < 2 * E) atomicAdd(&cntP[__ldg(&vp_d[i - E])], 1);
}

// per-block exclusive scan of 1024 ints; block total to part[]
__global__ void scan_local_kernel(const int* __restrict__ cnt, int* __restrict__ row,
                                  int* __restrict__ part) {
    __shared__ int sm[256];
    int t = threadIdx.x;
    int base = blockIdx.x * 1024 + t * 4;
    int4 v = *(const int4*)(cnt + base);
    int tsum = v.x + v.y + v.z + v.w;
    sm[t] = tsum;
    __syncthreads();
    #pragma unroll
    for (int off = 1; off < 256; off <<= 1) {
        int add = (t >= off) ? sm[t - off] : 0;
        __syncthreads();
        sm[t] += add;
        __syncthreads();
    }
    int excl = sm[t] - tsum;
    int r1 = excl + v.x, r2 = r1 + v.y, r3 = r2 + v.z;
    *(int4*)(row + base) = make_int4(excl, r1, r2, r3);
    if (t == 255) part[blockIdx.x] = sm[255];
}

// single-block exclusive scan of M (<=1024) partials, in place
__global__ void scan_part_kernel(int* __restrict__ part, int M) {
    __shared__ int sm[1024];
    int t = threadIdx.x;
    int orig = (t < M) ? part[t] : 0;
    sm[t] = orig;
    __syncthreads();
    #pragma unroll
    for (int off = 1; off < 1024; off <<= 1) {
        int add = (t >= off) ? sm[t - off] : 0;
        __syncthreads();
        sm[t] += add;
        __syncthreads();
    }
    if (t < M) part[t] = sm[t] - orig;
}

__global__ void scan_add_kernel(int* __restrict__ row, const int* __restrict__ part,
                                int* __restrict__ cur, int Npad) {
    int i = blockIdx.x * blockDim.x + threadIdx.x;
    if (i >= Npad) return;
    int r = row[i] + __ldg(&part[i >> 10]);
    row[i] = r;
    cur[i] = r;
}

__global__ void scatter_kernel(const int* __restrict__ pv_s, const int* __restrict__ pv_d,
                               const int* __restrict__ vp_s, const int* __restrict__ vp_d,
                               int* __restrict__ curQ, int* __restrict__ curP,
                               int* __restrict__ ssrc0, int* __restrict__ ssrc1, int E) {
    int i = blockIdx.x * blockDim.x + threadIdx.x;
    if (i < E) {
        int pos = atomicAdd(&curQ[__ldg(&pv_d[i])], 1);
        ssrc0[pos] = __ldg(&pv_s[i]);
    } else if (i < 2 * E) {
        int j = i - E;
        int pos = atomicAdd(&curP[__ldg(&vp_d[j])], 1);
        ssrc1[pos] = __ldg(&vp_s[j]);
    }
}

// ------------------------- dense kernels (R2-proven) -------------------------
__global__ void wvec2_kernel(const float* __restrict__ Wd0, const float* __restrict__ Wd1,
                             const float* __restrict__ avd0, const float* __restrict__ avd1,
                             float* __restrict__ wvec) {
    int t = threadIdx.x;
    const float* W = (t < 64) ? Wd0 : Wd1;
    const float* a = (t < 64) ? avd0 : avd1;
    int k = t & 63;
    float s = 0.f;
    #pragma unroll
    for (int c = 0; c < CDIM; c++) s = fmaf(W[k * CDIM + c], a[c], s);
    wvec[t] = s;
}

template <bool ELU>
__global__ __launch_bounds__(128) void gemm_kernel(
    const float* __restrict__ X, const float* __restrict__ W,
    const float* __restrict__ avs, const float* __restrict__ wvec,
    float* __restrict__ H, float* __restrict__ als, float* __restrict__ ald, int N)
{
    __shared__ float xT[64 * 128];
    __shared__ float ws[64 * 64];
    const int tid  = threadIdx.x;
    const int row0 = blockIdx.x * 128;

    {
        const float4* Wv = (const float4*)W;
        float4* wsv = (float4*)ws;
        #pragma unroll
        for (int i = 0; i < 8; i++) wsv[i * 128 + tid] = Wv[i * 128 + tid];
    }
    {
        int row = row0 + tid;
        if (row < N) {
            const float4* Xv = (const float4*)(X + (size_t)row * CDIM);
            #pragma unroll
            for (int j = 0; j < 16; j++) {
                float4 v = Xv[j];
                if (ELU) {
                    v.x = (v.x > 0.f) ? v.x : expm1f(v.x);
                    v.y = (v.y > 0.f) ? v.y : expm1f(v.y);
                    v.z = (v.z > 0.f) ? v.z : expm1f(v.z);
                    v.w = (v.w > 0.f) ? v.w : expm1f(v.w);
                }
                xT[(4 * j + 0) * 128 + tid] = v.x;
                xT[(4 * j + 1) * 128 + tid] = v.y;
                xT[(4 * j + 2) * 128 + tid] = v.z;
                xT[(4 * j + 3) * 128 + tid] = v.w;
            }
        } else {
            #pragma unroll
            for (int j = 0; j < 64; j++) xT[j * 128 + tid] = 0.f;
        }
    }
    __syncthreads();

    const int ty = tid >> 3;
    const int tx = tid & 7;
    unsigned long long acc[8][4];
    #pragma unroll
    for (int i = 0; i < 8; i++)
        #pragma unroll
        for (int j = 0; j < 4; j++) acc[i][j] = 0ull;

    #pragma unroll 4
    for (int k = 0; k < 64; k++) {
        float4 a0 = *(const float4*)&xT[k * 128 + ty * 8];
        float4 a1 = *(const float4*)&xT[k * 128 + ty * 8 + 4];
        float4 b0 = *(const float4*)&ws[k * 64 + tx * 8];
        float4 b1 = *(const float4*)&ws[k * 64 + tx * 8 + 4];
        unsigned long long bp[4] = {pack2(b0.x, b0.y), pack2(b0.z, b0.w),
                                    pack2(b1.x, b1.y), pack2(b1.z, b1.w)};
        float a[8] = {a0.x, a0.y, a0.z, a0.w, a1.x, a1.y, a1.z, a1.w};
        #pragma unroll
        for (int i = 0; i < 8; i++) {
            unsigned long long ap = pack2(a[i], a[i]);
            #pragma unroll
            for (int j = 0; j < 4; j++) fma2(acc[i][j], ap, bp[j]);
        }
    }

    unsigned long long avp[4];
    {
        float4 av0 = __ldg((const float4*)avs + tx * 2);
        float4 av1 = __ldg((const float4*)avs + tx * 2 + 1);
        avp[0] = pack2(av0.x, av0.y); avp[1] = pack2(av0.z, av0.w);
        avp[2] = pack2(av1.x, av1.y); avp[3] = pack2(av1.z, av1.w);
    }

    #pragma unroll
    for (int i = 0; i < 8; i++) {
        int row = row0 + ty * 8 + i;
        unsigned long long alp = 0ull;
        #pragma unroll
        for (int j = 0; j < 4; j++) fma2(alp, acc[i][j], avp[j]);
        float2 f = unpack2(alp);
        float al = f.x + f.y;
        al += __shfl_down_sync(0xffffffffu, al, 4);
        al += __shfl_down_sync(0xffffffffu, al, 2);
        al += __shfl_down_sync(0xffffffffu, al, 1);
        if (row < N) {
            ulonglong2* Hp = (ulonglong2*)(H + (size_t)row * CDIM + tx * 8);
            Hp[0] = make_ulonglong2(acc[i][0], acc[i][1]);
            Hp[1] = make_ulonglong2(acc[i][2], acc[i][3]);
            if (tx == 0) als[row] = al;
        }
    }

    {
        float s = 0.f;
        #pragma unroll
        for (int k = 0; k < 64; k++) s = fmaf(xT[k * 128 + tid], __ldg(&wvec[k]), s);
        int row = row0 + tid;
        if (row < N) ald[row] = s;
    }
}

// ------------------------- CSR GAT aggregation: one warp per dst row, no atomics ----
// out[d] = (elu?)( bias + sum_e (ex_e / den) * hs[src_e] ),  ex = exp(lrelu(als[src]+ald[d]))
template <bool ELUOUT>
__global__ __launch_bounds__(256) void gat_kernel(
    const int* __restrict__ row, const int* __restrict__ cnt, const int* __restrict__ ssrc,
    const float* __restrict__ als, const float* __restrict__ ald,
    const float* __restrict__ hs, const float* __restrict__ bias,
    float* __restrict__ out, int Nd)
{
    int w = (blockIdx.x * blockDim.x + threadIdx.x) >> 5;
    if (w >= Nd) return;
    int lane = threadIdx.x & 31;
    int start = __ldg(&row[w]);
    int deg   = __ldg(&cnt[w]);

    float2 bv = __ldg((const float2*)bias + lane);
    if (deg == 0) {
        if (ELUOUT) {
            bv.x = (bv.x > 0.f) ? bv.x : expm1f(bv.x);
            bv.y = (bv.y > 0.f) ? bv.y : expm1f(bv.y);
        }
        ((float2*)(out + (size_t)w * CDIM))[lane] = bv;
        return;
    }

    float aldv = __ldg(&ald[w]);

    // pass 1: den
    float den = 0.f;
    for (int c0 = 0; c0 < deg; c0 += 32) {
        int e = c0 + lane;
        float ex = 0.f;
        if (e < deg) {
            int s = __ldg(&ssrc[start + e]);
            float v = __ldg(&als[s]) + aldv;
            v = (v >= 0.f) ? v : 0.2f * v;
            ex = __expf(fminf(v, 80.f));
        }
        #pragma unroll
        for (int off = 16; off > 0; off >>= 1) ex += __shfl_xor_sync(0xffffffffu, ex, off);
        den += ex;
    }
    float inv = 1.f / den;

    // pass 2: weighted gather-accumulate (coalesced 256B rows; 2-deep MLP)
    float2 acc = bv;
    for (int c0 = 0; c0 < deg; c0 += 32) {
        int e = c0 + lane;
        int s = 0; float ex = 0.f;
        if (e < deg) {
            s = __ldg(&ssrc[start + e]);
            float v = __ldg(&als[s]) + aldv;
            v = (v >= 0.f) ? v : 0.2f * v;
            ex = __expf(fminf(v, 80.f));
        }
        int m = min(32, deg - c0);
        int j = 0;
        for (; j + 2 <= m; j += 2) {
            float a0 = __shfl_sync(0xffffffffu, ex, j) * inv;
            int   s0 = __shfl_sync(0xffffffffu, s, j);
            float a1 = __shfl_sync(0xffffffffu, ex, j + 1) * inv;
            int   s1 = __shfl_sync(0xffffffffu, s, j + 1);
            float2 h0 = __ldg((const float2*)(hs + (size_t)s0 * CDIM) + lane);
            float2 h1 = __ldg((const float2*)(hs + (size_t)s1 * CDIM) + lane);
            acc.x = fmaf(a0, h0.x, acc.x); acc.y = fmaf(a0, h0.y, acc.y);
            acc.x = fmaf(a1, h1.x, acc.x); acc.y = fmaf(a1, h1.y, acc.y);
        }
        if (j < m) {
            float a0 = __shfl_sync(0xffffffffu, ex, j) * inv;
            int   s0 = __shfl_sync(0xffffffffu, s, j);
            float2 h0 = __ldg((const float2*)(hs + (size_t)s0 * CDIM) + lane);
            acc.x = fmaf(a0, h0.x, acc.x); acc.y = fmaf(a0, h0.y, acc.y);
        }
    }
    if (ELUOUT) {
        acc.x = (acc.x > 0.f) ? acc.x : expm1f(acc.x);
        acc.y = (acc.y > 0.f) ? acc.y : expm1f(acc.y);
    }
    ((float2*)(out + (size_t)w * CDIM))[lane] = acc;
}

// ------------------------- host orchestration -------------------------
extern "C" void kernel_launch(void* const* d_in, const int* in_sizes, int n_in,
                              void* d_out, int out_size)
{
    const float* xp   = (const float*)d_in[0];
    const float* xq   = (const float*)d_in[1];
    const int*   pv_s = (const int*)d_in[2];
    const int*   pv_d = (const int*)d_in[3];
    const int*   vp_s = (const int*)d_in[4];
    const int*   vp_d = (const int*)d_in[5];
    const float* Wsrc = (const float*)d_in[6];
    const float* Wdst = (const float*)d_in[7];
    const float* asrc = (const float*)d_in[8];
    const float* adst = (const float*)d_in[9];
    const float* bias = (const float*)d_in[10];
    int E = in_sizes[2];

    float *hsP, *hsQ, *hp1, *hq1, *alsP, *aldP, *alsQ, *aldQ, *wvec;
    int *cntQ, *cntP, *rowQ, *rowP, *curQ, *curP, *partQ, *partP, *ssrc0, *ssrc1;
    cudaGetSymbolAddress((void**)&hsP,   g_hsP);
    cudaGetSymbolAddress((void**)&hsQ,   g_hsQ);
    cudaGetSymbolAddress((void**)&hp1,   g_hp1);
    cudaGetSymbolAddress((void**)&hq1,   g_hq1);
    cudaGetSymbolAddress((void**)&alsP,  g_alsP);
    cudaGetSymbolAddress((void**)&aldP,  g_aldP);
    cudaGetSymbolAddress((void**)&alsQ,  g_alsQ);
    cudaGetSymbolAddress((void**)&aldQ,  g_aldQ);
    cudaGetSymbolAddress((void**)&wvec,  g_wvec);
    cudaGetSymbolAddress((void**)&cntQ,  g_cntQ);
    cudaGetSymbolAddress((void**)&cntP,  g_cntP);
    cudaGetSymbolAddress((void**)&rowQ,  g_rowQ);
    cudaGetSymbolAddress((void**)&rowP,  g_rowP);
    cudaGetSymbolAddress((void**)&curQ,  g_curQ);
    cudaGetSymbolAddress((void**)&curP,  g_curP);
    cudaGetSymbolAddress((void**)&partQ, g_partQ);
    cudaGetSymbolAddress((void**)&partP, g_partP);
    cudaGetSymbolAddress((void**)&ssrc0, g_ssrc0);
    cudaGetSymbolAddress((void**)&ssrc1, g_ssrc1);

    float* outp = (float*)d_out;
    float* outq = (float*)d_out + (size_t)NP * CDIM;

    const unsigned gP  = (NP + 127) / 128, gQ = (NQ + 127) / 128;
    const unsigned gGP = (unsigned)(((long)NP * 32 + 255) / 256);
    const unsigned gGQ = (unsigned)(((long)NQ * 32 + 255) / 256);
    const unsigned gE2 = (2 * E + 255) / 256;

    // ---- CSR build (once; reused by both layers) ----
    zero_kernel<<<(NQPAD + NPPAD + 255) / 256, 256>>>(cntQ, cntP);
    hist_kernel<<<gE2, 256>>>(pv_d, vp_d, cntQ, cntP, E);
    scan_local_kernel<<<MQ, 256>>>(cntQ, rowQ, partQ);
    scan_local_kernel<<<MP, 256>>>(cntP, rowP, partP);
    scan_part_kernel<<<1, 1024>>>(partQ, MQ);
    scan_part_kernel<<<1, 1024>>>(partP, MP);
    scan_add_kernel<<<NQPAD / 256, 256>>>(rowQ, partQ, curQ, NQPAD);
    scan_add_kernel<<<NPPAD / 256, 256>>>(rowP, partP, curP, NPPAD);
    scatter_kernel<<<gE2, 256>>>(pv_s, pv_d, vp_s, vp_d, curQ, curP, ssrc0, ssrc1, E);

    // ---- layer 0 ----
    wvec2_kernel<<<1, 128>>>(Wdst + 0 * 4096, Wdst + 1 * 4096, adst + 0 * 64, adst + 1 * 64, wvec);
    gemm_kernel<false><<<gP, 128>>>(xp, Wsrc + 0 * 4096, asrc + 0 * 64, wvec + 64,
                                    hsP, alsP, aldP, NP);
    gemm_kernel<false><<<gQ, 128>>>(xq, Wsrc + 1 * 4096, asrc + 1 * 64, wvec,
                                    hsQ, alsQ, aldQ, NQ);
    // conv1 first (hsQ L2-hot), then conv0
    gat_kernel<false><<<gGP, 256>>>(rowP, cntP, ssrc1, alsQ, aldP, hsQ, bias + 1 * 64, hp1, NP);
    gat_kernel<false><<<gGQ, 256>>>(rowQ, cntQ, ssrc0, alsP, aldQ, hsP, bias + 0 * 64, hq1, NQ);

    // ---- layer 1 (ELU on load; ELU folded into output store) ----
    wvec2_kernel<<<1, 128>>>(Wdst + 2 * 4096, Wdst + 3 * 4096, adst + 2 * 64, adst + 3 * 64, wvec);
    gemm_kernel<true><<<gP, 128>>>(hp1, Wsrc + 2 * 4096, asrc + 2 * 64, wvec + 64,
                                   hsP, alsP, aldP, NP);
    gemm_kernel<true><<<gQ, 128>>>(hq1, Wsrc + 3 * 4096, asrc + 3 * 64, wvec,
                                   hsQ, alsQ, aldQ, NQ);
    gat_kernel<true><<<gGP, 256>>>(rowP, cntP, ssrc1, alsQ, aldP, hsQ, bias + 3 * 64, outp, NP);
    gat_kernel<true><<<gGQ, 256>>>(rowQ, cntQ, ssrc0, alsP, aldQ, hsP, bias + 2 * 64, outq, NQ);
}